// round 1
// baseline (speedup 1.0000x reference)
#include <cuda_runtime.h>
#include <cstdint>

#define D_MODEL 1024
#define N_HEADS 16
#define HEAD_DIM 64
#define BATCH 4
#define SEQ 2048
#define M_TOT 8192  // BATCH*SEQ

// Scratch (allocation-free rule: device globals)
__device__ float g_Q[M_TOT * D_MODEL];
__device__ float g_K[M_TOT * D_MODEL];
__device__ float g_V[M_TOT * D_MODEL];
__device__ float g_ATT[M_TOT * D_MODEL];

// ---------- helpers ----------
__device__ __forceinline__ void split_tf32(float f, uint32_t &hi, uint32_t &lo) {
    asm volatile("cvt.rna.tf32.f32 %0, %1;" : "=r"(hi) : "f"(f));
    float r = f - __uint_as_float(hi);
    asm volatile("cvt.rna.tf32.f32 %0, %1;" : "=r"(lo) : "f"(r));
}

__device__ __forceinline__ void mma_tf32(float c[4], uint32_t a0, uint32_t a1, uint32_t a2, uint32_t a3,
                                         uint32_t b0, uint32_t b1) {
    asm volatile(
        "mma.sync.aligned.m16n8k8.row.col.f32.tf32.tf32.f32 "
        "{%0,%1,%2,%3}, {%4,%5,%6,%7}, {%8,%9}, {%0,%1,%2,%3};\n"
        : "+f"(c[0]), "+f"(c[1]), "+f"(c[2]), "+f"(c[3])
        : "r"(a0), "r"(a1), "r"(a2), "r"(a3), "r"(b0), "r"(b1));
}

__device__ __forceinline__ void cpa16(void *s, const void *g) {
    uint32_t sa = (uint32_t)__cvta_generic_to_shared(s);
    asm volatile("cp.async.cg.shared.global [%0], [%1], 16;\n" ::"r"(sa), "l"(g));
}

// ---------- GEMM: C[m,n] = sum_k A[m,k] * B[n,k]  (both K-contiguous, M=8192, N=K=1024) ----------
#define BM 128
#define BN 128
#define BK 32
#define LDA 36
#define GEMM_SMEM (2 * (BM + BN) * LDA * 4)

__global__ void __launch_bounds__(256) gemm_tn_kernel(const float *__restrict__ A, const float *__restrict__ B,
                                                      float *__restrict__ C, int scatter) {
    extern __shared__ float sm[];
    float *As = sm;
    float *Bs = sm + 2 * BM * LDA;
    const int tid = threadIdx.x;
    const int lane = tid & 31, w = tid >> 5;
    const int m0 = blockIdx.y * BM, n0 = blockIdx.x * BN;
    const int wm = (w >> 2) * 64, wn = (w & 3) * 32;  // 2x4 warp grid, 64x32 warp tile

    float acc[4][4][4];
#pragma unroll
    for (int i = 0; i < 4; i++)
#pragma unroll
        for (int j = 0; j < 4; j++)
#pragma unroll
            for (int k = 0; k < 4; k++) acc[i][j][k] = 0.f;

    auto loadTiles = [&](int kt, int stg) {
        const float *Ag = A + (size_t)m0 * 1024 + kt * BK;
        const float *Bg = B + (size_t)n0 * 1024 + kt * BK;
        float *Ad = As + stg * BM * LDA;
        float *Bd = Bs + stg * BN * LDA;
#pragma unroll
        for (int i = 0; i < 4; i++) {
            int lin = tid + i * 256;
            int r = lin >> 3, c = (lin & 7) << 2;
            cpa16(Ad + r * LDA + c, Ag + (size_t)r * 1024 + c);
            cpa16(Bd + r * LDA + c, Bg + (size_t)r * 1024 + c);
        }
    };

    loadTiles(0, 0);
    asm volatile("cp.async.commit_group;\n");

    const int gr = lane >> 2, gc = lane & 3;
    for (int kt = 0; kt < 1024 / BK; ++kt) {
        asm volatile("cp.async.wait_group 0;\n");
        __syncthreads();
        if (kt + 1 < 1024 / BK) {
            loadTiles(kt + 1, (kt + 1) & 1);
            asm volatile("cp.async.commit_group;\n");
        }
        const float *Ad = As + (kt & 1) * BM * LDA;
        const float *Bd = Bs + (kt & 1) * BN * LDA;
#pragma unroll
        for (int kk = 0; kk < BK; kk += 8) {
            uint32_t ah[4][4], alo[4][4], bhf[4][2], blf[4][2];
#pragma unroll
            for (int im = 0; im < 4; im++) {
                const float *p = Ad + (wm + im * 16 + gr) * LDA + kk + gc;
                split_tf32(p[0], ah[im][0], alo[im][0]);
                split_tf32(p[8 * LDA], ah[im][1], alo[im][1]);
                split_tf32(p[4], ah[im][2], alo[im][2]);
                split_tf32(p[8 * LDA + 4], ah[im][3], alo[im][3]);
            }
#pragma unroll
            for (int in = 0; in < 4; in++) {
                const float *p = Bd + (wn + in * 8 + gr) * LDA + kk + gc;
                split_tf32(p[0], bhf[in][0], blf[in][0]);
                split_tf32(p[4], bhf[in][1], blf[in][1]);
            }
#pragma unroll
            for (int im = 0; im < 4; im++)
#pragma unroll
                for (int in = 0; in < 4; in++) {
                    mma_tf32(acc[im][in], ah[im][0], ah[im][1], ah[im][2], ah[im][3], bhf[in][0], bhf[in][1]);
                    mma_tf32(acc[im][in], alo[im][0], alo[im][1], alo[im][2], alo[im][3], bhf[in][0], bhf[in][1]);
                    mma_tf32(acc[im][in], ah[im][0], ah[im][1], ah[im][2], ah[im][3], blf[in][0], blf[in][1]);
                }
        }
        __syncthreads();
    }

#pragma unroll
    for (int im = 0; im < 4; im++)
#pragma unroll
        for (int in = 0; in < 4; in++)
#pragma unroll
            for (int j = 0; j < 4; j++) {
                int gm = m0 + wm + im * 16 + gr + ((j >= 2) ? 8 : 0);
                int gn = n0 + wn + in * 8 + gc * 2 + (j & 1);
                float v = acc[im][in][j];
                if (scatter) {
                    // scatter (m = b*S+s, n = h*64+d) -> (B,H,S,Dh)
                    int b = gm >> 11, s = gm & 2047, h = gn >> 6, d = gn & 63;
                    C[(((size_t)(b * N_HEADS + h) * SEQ + s) << 6) + d] = v;
                } else {
                    C[(size_t)gm * D_MODEL + gn] = v;
                }
            }
}

// ---------- Flash attention: 1 CTA per (b*h, q-tile of 128). 8 warps x (16 q-rows, full 128 k-cols) ----------
#define LDQ 68
#define LDV 132
#define ATTN_SMEM ((2 * 128 * LDQ + 64 * LDV + 8 * 16 * LDV) * 4)

__global__ void __launch_bounds__(256) attn_kernel(const float *__restrict__ Q, const float *__restrict__ K,
                                                   const float *__restrict__ V, float *__restrict__ O) {
    extern __shared__ float sm[];
    float *Qs = sm;                  // [128][LDQ]
    float *Ks = Qs + 128 * LDQ;      // [128][LDQ]
    float *Vt = Ks + 128 * LDQ;      // [64][LDV]  (transposed V: rows=d, cols=kv)
    float *Ps = Vt + 64 * LDV;       // 8 warps x [16][LDV]
    const int tid = threadIdx.x, lane = tid & 31, w = tid >> 5;
    const int qt = blockIdx.x, bh = blockIdx.y;
    const size_t headBase = (size_t)bh * SEQ * HEAD_DIM;
    const int gr = lane >> 2, gc = lane & 3;

    {   // Q tile (once)
        const float *g = Q + headBase + (size_t)qt * 128 * HEAD_DIM;
#pragma unroll
        for (int i = 0; i < 8; i++) {
            int lin = tid + i * 256;
            int r = lin >> 4, c = (lin & 15) << 2;
            *(float4 *)(Qs + r * LDQ + c) = *(const float4 *)(g + r * HEAD_DIM + c);
        }
    }

    float accO[8][4];
#pragma unroll
    for (int i = 0; i < 8; i++)
#pragma unroll
        for (int j = 0; j < 4; j++) accO[i][j] = 0.f;
    float m0r = -1e30f, m1r = -1e30f, l0 = 0.f, l1 = 0.f;
    float *myP = Ps + w * 16 * LDV;

    for (int kt = 0; kt <= qt; ++kt) {
        __syncthreads();  // also covers initial Qs visibility; protects Ks/Vt reuse
        {
            const float *gk = K + headBase + (size_t)kt * 128 * HEAD_DIM;
            const float *gv = V + headBase + (size_t)kt * 128 * HEAD_DIM;
#pragma unroll
            for (int i = 0; i < 8; i++) {
                int lin = tid + i * 256;
                int r = lin >> 4, c = (lin & 15) << 2;
                *(float4 *)(Ks + r * LDQ + c) = *(const float4 *)(gk + r * HEAD_DIM + c);
                float4 v = *(const float4 *)(gv + r * HEAD_DIM + c);
                Vt[(c + 0) * LDV + r] = v.x;
                Vt[(c + 1) * LDV + r] = v.y;
                Vt[(c + 2) * LDV + r] = v.z;
                Vt[(c + 3) * LDV + r] = v.w;
            }
        }
        __syncthreads();

        // S = Q K^T  (warp owns rows [w*16, w*16+16), all 128 cols)
        float s[16][4];
#pragma unroll
        for (int nt = 0; nt < 16; nt++)
#pragma unroll
            for (int j = 0; j < 4; j++) s[nt][j] = 0.f;

#pragma unroll
        for (int kk = 0; kk < 64; kk += 8) {
            uint32_t ah[4], alo[4];
            const float *ap = Qs + (w * 16 + gr) * LDQ + kk + gc;
            split_tf32(ap[0], ah[0], alo[0]);
            split_tf32(ap[8 * LDQ], ah[1], alo[1]);
            split_tf32(ap[4], ah[2], alo[2]);
            split_tf32(ap[8 * LDQ + 4], ah[3], alo[3]);
#pragma unroll
            for (int nt = 0; nt < 16; nt++) {
                const float *bp = Ks + (nt * 8 + gr) * LDQ + kk + gc;
                uint32_t b0h, b0l, b1h, b1l;
                split_tf32(bp[0], b0h, b0l);
                split_tf32(bp[4], b1h, b1l);
                mma_tf32(s[nt], ah[0], ah[1], ah[2], ah[3], b0h, b1h);
                mma_tf32(s[nt], alo[0], alo[1], alo[2], alo[3], b0h, b1h);
                mma_tf32(s[nt], ah[0], ah[1], ah[2], ah[3], b0l, b1l);
            }
        }

        // scale + causal mask + row stats
        const bool diag = (kt == qt);
        const int qg0 = qt * 128 + w * 16 + gr;
        float mx0 = -1e30f, mx1 = -1e30f;
#pragma unroll
        for (int nt = 0; nt < 16; nt++) {
            int kg = kt * 128 + nt * 8 + gc * 2;
#pragma unroll
            for (int j = 0; j < 4; j++) {
                float v = s[nt][j] * 0.125f;  // 1/sqrt(64)
                if (diag && (kg + (j & 1)) > (qg0 + ((j >= 2) ? 8 : 0))) v = -1e30f;
                s[nt][j] = v;
            }
            mx0 = fmaxf(mx0, fmaxf(s[nt][0], s[nt][1]));
            mx1 = fmaxf(mx1, fmaxf(s[nt][2], s[nt][3]));
        }
        mx0 = fmaxf(mx0, __shfl_xor_sync(0xffffffffu, mx0, 1));
        mx0 = fmaxf(mx0, __shfl_xor_sync(0xffffffffu, mx0, 2));
        mx1 = fmaxf(mx1, __shfl_xor_sync(0xffffffffu, mx1, 1));
        mx1 = fmaxf(mx1, __shfl_xor_sync(0xffffffffu, mx1, 2));
        float mn0 = fmaxf(m0r, mx0), mn1 = fmaxf(m1r, mx1);
        float alpha0 = __expf(m0r - mn0), alpha1 = __expf(m1r - mn1);
        m0r = mn0; m1r = mn1;

        float rs0 = 0.f, rs1 = 0.f;
#pragma unroll
        for (int nt = 0; nt < 16; nt++) {
            float p0 = __expf(s[nt][0] - mn0);
            float p1 = __expf(s[nt][1] - mn0);
            float p2 = __expf(s[nt][2] - mn1);
            float p3 = __expf(s[nt][3] - mn1);
            rs0 += p0 + p1;
            rs1 += p2 + p3;
            int col = nt * 8 + gc * 2;
            myP[gr * LDV + col] = p0;
            myP[gr * LDV + col + 1] = p1;
            myP[(gr + 8) * LDV + col] = p2;
            myP[(gr + 8) * LDV + col + 1] = p3;
        }
        rs0 += __shfl_xor_sync(0xffffffffu, rs0, 1);
        rs0 += __shfl_xor_sync(0xffffffffu, rs0, 2);
        rs1 += __shfl_xor_sync(0xffffffffu, rs1, 1);
        rs1 += __shfl_xor_sync(0xffffffffu, rs1, 2);
        l0 = l0 * alpha0 + rs0;
        l1 = l1 * alpha1 + rs1;
#pragma unroll
        for (int nt = 0; nt < 8; nt++) {
            accO[nt][0] *= alpha0; accO[nt][1] *= alpha0;
            accO[nt][2] *= alpha1; accO[nt][3] *= alpha1;
        }
        __syncwarp();  // order own-warp P stores before re-reading as A fragments

        // O += P V
#pragma unroll
        for (int kk = 0; kk < 128; kk += 8) {
            uint32_t ah[4], alo[4];
            const float *ap = myP + gr * LDV + kk + gc;
            split_tf32(ap[0], ah[0], alo[0]);
            split_tf32(ap[8 * LDV], ah[1], alo[1]);
            split_tf32(ap[4], ah[2], alo[2]);
            split_tf32(ap[8 * LDV + 4], ah[3], alo[3]);
#pragma unroll
            for (int nt = 0; nt < 8; nt++) {
                const float *bp = Vt + (nt * 8 + gr) * LDV + kk + gc;
                uint32_t b0h, b0l, b1h, b1l;
                split_tf32(bp[0], b0h, b0l);
                split_tf32(bp[4], b1h, b1l);
                mma_tf32(accO[nt], ah[0], ah[1], ah[2], ah[3], b0h, b1h);
                mma_tf32(accO[nt], alo[0], alo[1], alo[2], alo[3], b0h, b1h);
                mma_tf32(accO[nt], ah[0], ah[1], ah[2], ah[3], b0l, b1l);
            }
        }
    }

    // finalize: O/l, write concat layout (B,S,D)
    float inv0 = 1.f / l0, inv1 = 1.f / l1;
    int b = bh >> 4, h = bh & 15;
    int q0 = qt * 128 + w * 16 + gr;
#pragma unroll
    for (int nt = 0; nt < 8; nt++) {
        int col = h * 64 + nt * 8 + gc * 2;
        float *o0 = O + (size_t)(b * SEQ + q0) * D_MODEL + col;
        o0[0] = accO[nt][0] * inv0;
        o0[1] = accO[nt][1] * inv0;
        float *o1 = o0 + (size_t)8 * D_MODEL;
        o1[0] = accO[nt][2] * inv1;
        o1[1] = accO[nt][3] * inv1;
    }
}

// ---------- launch ----------
extern "C" void kernel_launch(void *const *d_in, const int *in_sizes, int n_in, void *d_out, int out_size) {
    const float *x  = (const float *)d_in[0];
    const float *Wq = (const float *)d_in[1];
    const float *Wk = (const float *)d_in[2];
    const float *Wv = (const float *)d_in[3];
    const float *Wo = (const float *)d_in[4];
    float *out = (float *)d_out;

    float *pQ, *pK, *pV, *pA;
    cudaGetSymbolAddress((void **)&pQ, g_Q);
    cudaGetSymbolAddress((void **)&pK, g_K);
    cudaGetSymbolAddress((void **)&pV, g_V);
    cudaGetSymbolAddress((void **)&pA, g_ATT);

    cudaFuncSetAttribute(gemm_tn_kernel, cudaFuncAttributeMaxDynamicSharedMemorySize, GEMM_SMEM);
    cudaFuncSetAttribute(attn_kernel, cudaFuncAttributeMaxDynamicSharedMemorySize, ATTN_SMEM);

    dim3 gg(D_MODEL / BN, M_TOT / BM);  // (8, 64)
    gemm_tn_kernel<<<gg, 256, GEMM_SMEM>>>(x, Wq, pQ, 1);
    gemm_tn_kernel<<<gg, 256, GEMM_SMEM>>>(x, Wk, pK, 1);
    gemm_tn_kernel<<<gg, 256, GEMM_SMEM>>>(x, Wv, pV, 1);
    attn_kernel<<<dim3(SEQ / 128, BATCH * N_HEADS), 256, ATTN_SMEM>>>(pQ, pK, pV, pA);
    gemm_tn_kernel<<<gg, 256, GEMM_SMEM>>>(pA, Wo, out, 0);
}

// round 3
// speedup vs baseline: 1.5828x; 1.5828x over previous
#include <cuda_runtime.h>
#include <cuda_bf16.h>
#include <cstdint>

#define D_MODEL 1024
#define N_HEADS 16
#define HEAD_DIM 64
#define BATCH 4
#define SEQ 2048
#define M_TOT 8192  // BATCH*SEQ

// ---- scratch (device globals per allocation-free rule) ----
__device__ uint2 g_xs[M_TOT * 512];          // x split, interleaved {hi2,lo2} per k-pair
__device__ uint2 g_Ws[4][D_MODEL * 512];     // Wq,Wk,Wv,Wo split
__device__ uint2 g_Qh[M_TOT * 512];          // Q scatter (B,H,S,32) interleaved
__device__ uint2 g_Kh[M_TOT * 512];          // K scatter
__device__ float g_Vf[M_TOT * D_MODEL];      // V scatter fp32 (B,H,S,64)
__device__ uint2 g_Ah[M_TOT * 512];          // attention out, split, (B,S,D/2)

// ---------- helpers ----------
__device__ __forceinline__ uint2 split2(float f0, float f1) {
    __nv_bfloat16 h0 = __float2bfloat16_rn(f0), h1 = __float2bfloat16_rn(f1);
    float r0 = f0 - __bfloat162float(h0), r1 = f1 - __bfloat162float(h1);
    __nv_bfloat16 l0 = __float2bfloat16_rn(r0), l1 = __float2bfloat16_rn(r1);
    uint2 u;
    u.x = ((uint32_t)__bfloat16_as_ushort(h1) << 16) | __bfloat16_as_ushort(h0);
    u.y = ((uint32_t)__bfloat16_as_ushort(l1) << 16) | __bfloat16_as_ushort(l0);
    return u;
}

__device__ __forceinline__ void mma_bf16(float c[4], uint32_t a0, uint32_t a1, uint32_t a2, uint32_t a3,
                                         uint32_t b0, uint32_t b1) {
    asm volatile(
        "mma.sync.aligned.m16n8k16.row.col.f32.bf16.bf16.f32 "
        "{%0,%1,%2,%3}, {%4,%5,%6,%7}, {%8,%9}, {%0,%1,%2,%3};\n"
        : "+f"(c[0]), "+f"(c[1]), "+f"(c[2]), "+f"(c[3])
        : "r"(a0), "r"(a1), "r"(a2), "r"(a3), "r"(b0), "r"(b1));
}

__device__ __forceinline__ void cpa8(void *s, const void *g) {
    uint32_t sa = (uint32_t)__cvta_generic_to_shared(s);
    asm volatile("cp.async.ca.shared.global [%0], [%1], 8;\n" ::"r"(sa), "l"(g));
}

// ---------- split pass: fp32 -> interleaved {hi2,lo2} ----------
__global__ void __launch_bounds__(256) split_kernel(const float *__restrict__ src, uint2 *__restrict__ dst, int npairs) {
    int i = blockIdx.x * 256 + threadIdx.x;
    if (i < npairs) {
        float2 f = *(const float2 *)(src + 2 * (size_t)i);
        dst[i] = split2(f.x, f.y);
    }
}

// ---------- GEMM: C[m,n] = sum_k A[m,k]*B[n,k], bf16x3, operands pre-split ----------
#define LDAU 19  // u64 slots per row (16 data + 3 pad)
#define GEMM_SMEM (2 * 2 * 128 * LDAU * 8)

__global__ void __launch_bounds__(256) gemm_kernel(const uint2 *__restrict__ A, const uint2 *__restrict__ B,
                                                   void *__restrict__ Cout, int mode) {
    extern __shared__ uint2 smg[];
    uint2 *As = smg;                 // [2][128][LDAU]
    uint2 *Bs = smg + 2 * 128 * LDAU;
    const int tid = threadIdx.x, lane = tid & 31, w = tid >> 5;
    const int m0 = blockIdx.y * 128, n0 = blockIdx.x * 128;
    const int wm = (w >> 2) * 64, wn = (w & 3) * 32;
    const int gr = lane >> 2, gc = lane & 3;

    float acc[4][4][4];
#pragma unroll
    for (int i = 0; i < 4; i++)
#pragma unroll
        for (int j = 0; j < 4; j++)
#pragma unroll
            for (int k = 0; k < 4; k++) acc[i][j][k] = 0.f;

    auto load = [&](int kt, int stg) {
        const uint2 *Ag = A + (size_t)m0 * 512 + kt * 16;
        const uint2 *Bg = B + (size_t)n0 * 512 + kt * 16;
        uint2 *Ad = As + stg * 128 * LDAU;
        uint2 *Bd = Bs + stg * 128 * LDAU;
#pragma unroll
        for (int i = 0; i < 4; i++) {
            int id = tid + i * 256;
            int r = id >> 3, c = (id & 7) * 2;
            // 8-byte cp.async: shared row stride is odd (19*8B), so 16B ops would
            // be misaligned on odd rows. 8B ops are always aligned here.
            cpa8(Ad + r * LDAU + c, Ag + (size_t)r * 512 + c);
            cpa8(Ad + r * LDAU + c + 1, Ag + (size_t)r * 512 + c + 1);
            cpa8(Bd + r * LDAU + c, Bg + (size_t)r * 512 + c);
            cpa8(Bd + r * LDAU + c + 1, Bg + (size_t)r * 512 + c + 1);
        }
    };

    load(0, 0);
    asm volatile("cp.async.commit_group;\n");

    for (int kt = 0; kt < 32; ++kt) {
        asm volatile("cp.async.wait_group 0;\n");
        __syncthreads();
        if (kt + 1 < 32) {
            load(kt + 1, (kt + 1) & 1);
            asm volatile("cp.async.commit_group;\n");
        }
        const uint2 *Ad = As + (kt & 1) * 128 * LDAU;
        const uint2 *Bd = Bs + (kt & 1) * 128 * LDAU;
#pragma unroll
        for (int ks = 0; ks < 2; ks++) {
            const int so = ks * 8;
            uint32_t ahi[4][4], alo[4][4], bhi[4][2], blo[4][2];
#pragma unroll
            for (int im = 0; im < 4; im++) {
                const uint2 *p = Ad + (wm + im * 16 + gr) * LDAU + so + gc;
                uint2 v0 = p[0], v1 = p[8 * LDAU], v2 = p[4], v3 = p[8 * LDAU + 4];
                ahi[im][0] = v0.x; ahi[im][1] = v1.x; ahi[im][2] = v2.x; ahi[im][3] = v3.x;
                alo[im][0] = v0.y; alo[im][1] = v1.y; alo[im][2] = v2.y; alo[im][3] = v3.y;
            }
#pragma unroll
            for (int in = 0; in < 4; in++) {
                const uint2 *p = Bd + (wn + in * 8 + gr) * LDAU + so + gc;
                uint2 u0 = p[0], u1 = p[4];
                bhi[in][0] = u0.x; bhi[in][1] = u1.x;
                blo[in][0] = u0.y; blo[in][1] = u1.y;
            }
#pragma unroll
            for (int im = 0; im < 4; im++)
#pragma unroll
                for (int in = 0; in < 4; in++) {
                    mma_bf16(acc[im][in], ahi[im][0], ahi[im][1], ahi[im][2], ahi[im][3], bhi[in][0], bhi[in][1]);
                    mma_bf16(acc[im][in], alo[im][0], alo[im][1], alo[im][2], alo[im][3], bhi[in][0], bhi[in][1]);
                    mma_bf16(acc[im][in], ahi[im][0], ahi[im][1], ahi[im][2], ahi[im][3], blo[in][0], blo[in][1]);
                }
        }
        __syncthreads();
    }

#pragma unroll
    for (int im = 0; im < 4; im++)
#pragma unroll
        for (int in = 0; in < 4; in++) {
            int gm = m0 + wm + im * 16 + gr;
            int gn = n0 + wn + in * 8 + gc * 2;
            float c0 = acc[im][in][0], c1 = acc[im][in][1], c2 = acc[im][in][2], c3 = acc[im][in][3];
            if (mode == 0) {
                float *Cf = (float *)Cout;
                *(float2 *)(Cf + (size_t)gm * 1024 + gn) = make_float2(c0, c1);
                *(float2 *)(Cf + (size_t)(gm + 8) * 1024 + gn) = make_float2(c2, c3);
            } else {
                int b = gm >> 11, s2 = gm & 2047, h = gn >> 6, dd = gn & 63;
                if (mode == 1) {
                    uint2 *Ch = (uint2 *)Cout;
                    uint2 *dst = Ch + ((size_t)((b << 4) | h) * 2048 + s2) * 32 + (dd >> 1);
                    dst[0] = split2(c0, c1);
                    dst[8 * 32] = split2(c2, c3);
                } else {
                    float *Vf = (float *)Cout;
                    float *dst = Vf + ((size_t)((b << 4) | h) * 2048 + s2) * 64 + dd;
                    *(float2 *)dst = make_float2(c0, c1);
                    *(float2 *)(dst + 8 * 64) = make_float2(c2, c3);
                }
            }
        }
}

// ---------- Flash attention: q-tile 128 (8 warps x 16 rows), kv-tile 64, P in registers ----------
#define LQ 35
#define ATTN_SMEM ((128 * LQ + 64 * LQ + 64 * LQ) * 8)  // 71680

__global__ void __launch_bounds__(256, 2) attn_kernel(const uint2 *__restrict__ Q, const uint2 *__restrict__ K,
                                                      const float *__restrict__ V, uint2 *__restrict__ O) {
    extern __shared__ uint2 sma[];
    uint2 *Qs = sma;             // [128][LQ]
    uint2 *Ks = Qs + 128 * LQ;   // [64][LQ]
    uint2 *Vt = Ks + 64 * LQ;    // [64][LQ], rows=d, kv-pairs along row
    const int tid = threadIdx.x, lane = tid & 31, w = tid >> 5;
    const int qt = (int)gridDim.x - 1 - (int)blockIdx.x;  // long CTAs first
    const int bh = blockIdx.y;
    const int gr = lane >> 2, gc = lane & 3;
    const size_t hb = (size_t)bh * SEQ;

    {  // Q tile once
        const uint2 *Qg = Q + (hb + qt * 128) * 32;
#pragma unroll
        for (int i = 0; i < 16; i++) {
            int id = tid + i * 256;
            int r = id >> 5, c = id & 31;
            Qs[r * LQ + c] = Qg[r * 32 + c];
        }
    }

    float accO[8][4];
#pragma unroll
    for (int i = 0; i < 8; i++)
#pragma unroll
        for (int j = 0; j < 4; j++) accO[i][j] = 0.f;
    float m0r = -1e30f, m1r = -1e30f, l0 = 0.f, l1 = 0.f;
    const int qlast = qt * 128 + w * 16 + 15;
    const int nkt = 2 * qt + 2;

    for (int kt = 0; kt < nkt; ++kt) {
        __syncthreads();
        {
            const uint2 *Kg = K + (hb + kt * 64) * 32;
#pragma unroll
            for (int i = 0; i < 8; i++) {
                int id = tid + i * 256;
                int r = id >> 5, c = id & 31;
                Ks[r * LQ + c] = Kg[r * 32 + c];
            }
            const float *Vg = V + (hb + kt * 64) * 64;
            __nv_bfloat16 *Vb = (__nv_bfloat16 *)Vt;
#pragma unroll
            for (int i = 0; i < 4; i++) {
                int id = tid + i * 256;
                int r = id >> 4, c = (id & 15) * 4;
                float4 v = *(const float4 *)(Vg + r * 64 + c);
                float vv[4] = {v.x, v.y, v.z, v.w};
#pragma unroll
                for (int j = 0; j < 4; j++) {
                    __nv_bfloat16 h = __float2bfloat16_rn(vv[j]);
                    __nv_bfloat16 l = __float2bfloat16_rn(vv[j] - __bfloat162float(h));
                    int slot = (c + j) * LQ + (r >> 1);
                    Vb[slot * 4 + (r & 1)] = h;
                    Vb[slot * 4 + 2 + (r & 1)] = l;
                }
            }
        }
        __syncthreads();
        if (kt * 64 > qlast) continue;  // warp fully above diagonal

        // S = Q K^T (16 q-rows x 64 kv)
        float s[8][4];
#pragma unroll
        for (int nt = 0; nt < 8; nt++)
#pragma unroll
            for (int j = 0; j < 4; j++) s[nt][j] = 0.f;

#pragma unroll
        for (int ks = 0; ks < 4; ks++) {
            const int so = ks * 8;
            const uint2 *ap = Qs + (w * 16 + gr) * LQ + so + gc;
            uint2 a0 = ap[0], a1 = ap[8 * LQ], a2 = ap[4], a3 = ap[8 * LQ + 4];
#pragma unroll
            for (int nt = 0; nt < 8; nt++) {
                const uint2 *bp = Ks + (nt * 8 + gr) * LQ + so + gc;
                uint2 b0 = bp[0], b1 = bp[4];
                mma_bf16(s[nt], a0.x, a1.x, a2.x, a3.x, b0.x, b1.x);
                mma_bf16(s[nt], a0.y, a1.y, a2.y, a3.y, b0.x, b1.x);
                mma_bf16(s[nt], a0.x, a1.x, a2.x, a3.x, b0.y, b1.y);
            }
        }

        // scale + causal mask + row stats
        const bool needm = (kt * 64 + 63) > (qt * 128 + w * 16);
        const int qg0 = qt * 128 + w * 16 + gr;
        float mx0 = -1e30f, mx1 = -1e30f;
#pragma unroll
        for (int nt = 0; nt < 8; nt++) {
            int kg = kt * 64 + nt * 8 + gc * 2;
#pragma unroll
            for (int j = 0; j < 4; j++) {
                float v = s[nt][j] * 0.125f;
                if (needm && (kg + (j & 1)) > (qg0 + ((j >> 1) << 3))) v = -1e30f;
                s[nt][j] = v;
            }
            mx0 = fmaxf(mx0, fmaxf(s[nt][0], s[nt][1]));
            mx1 = fmaxf(mx1, fmaxf(s[nt][2], s[nt][3]));
        }
        mx0 = fmaxf(mx0, __shfl_xor_sync(0xffffffffu, mx0, 1));
        mx0 = fmaxf(mx0, __shfl_xor_sync(0xffffffffu, mx0, 2));
        mx1 = fmaxf(mx1, __shfl_xor_sync(0xffffffffu, mx1, 1));
        mx1 = fmaxf(mx1, __shfl_xor_sync(0xffffffffu, mx1, 2));
        float mn0 = fmaxf(m0r, mx0), mn1 = fmaxf(m1r, mx1);
        float alpha0 = __expf(m0r - mn0), alpha1 = __expf(m1r - mn1);
        m0r = mn0; m1r = mn1;

        float rs0 = 0.f, rs1 = 0.f;
#pragma unroll
        for (int nt = 0; nt < 8; nt++) {
            float p0 = __expf(s[nt][0] - mn0);
            float p1 = __expf(s[nt][1] - mn0);
            float p2 = __expf(s[nt][2] - mn1);
            float p3 = __expf(s[nt][3] - mn1);
            s[nt][0] = p0; s[nt][1] = p1; s[nt][2] = p2; s[nt][3] = p3;
            rs0 += p0 + p1;
            rs1 += p2 + p3;
        }
        rs0 += __shfl_xor_sync(0xffffffffu, rs0, 1);
        rs0 += __shfl_xor_sync(0xffffffffu, rs0, 2);
        rs1 += __shfl_xor_sync(0xffffffffu, rs1, 1);
        rs1 += __shfl_xor_sync(0xffffffffu, rs1, 2);
        l0 = l0 * alpha0 + rs0;
        l1 = l1 * alpha1 + rs1;
#pragma unroll
        for (int nt = 0; nt < 8; nt++) {
            accO[nt][0] *= alpha0; accO[nt][1] *= alpha0;
            accO[nt][2] *= alpha1; accO[nt][3] *= alpha1;
        }

        // O += P V (P packed to bf16 hi/lo in registers; S C-frag == PV A-frag layout)
#pragma unroll
        for (int t = 0; t < 4; t++) {
            uint2 u0 = split2(s[2 * t][0], s[2 * t][1]);
            uint2 u1 = split2(s[2 * t][2], s[2 * t][3]);
            uint2 u2 = split2(s[2 * t + 1][0], s[2 * t + 1][1]);
            uint2 u3 = split2(s[2 * t + 1][2], s[2 * t + 1][3]);
#pragma unroll
            for (int nt = 0; nt < 8; nt++) {
                const uint2 *bp = Vt + (nt * 8 + gr) * LQ + t * 8 + gc;
                uint2 b0 = bp[0], b1 = bp[4];
                mma_bf16(accO[nt], u0.x, u1.x, u2.x, u3.x, b0.x, b1.x);
                mma_bf16(accO[nt], u0.y, u1.y, u2.y, u3.y, b0.x, b1.x);
                mma_bf16(accO[nt], u0.x, u1.x, u2.x, u3.x, b0.y, b1.y);
            }
        }
    }

    // epilogue: write split interleaved concat layout (B,S,D/2)
    float inv0 = 1.f / l0, inv1 = 1.f / l1;
    int b = bh >> 4, h = bh & 15;
    int q0 = qt * 128 + w * 16 + gr;
#pragma unroll
    for (int nt = 0; nt < 8; nt++) {
        int slot = h * 32 + nt * 4 + gc;
        O[((size_t)(b * SEQ + q0)) * 512 + slot] = split2(accO[nt][0] * inv0, accO[nt][1] * inv0);
        O[((size_t)(b * SEQ + q0 + 8)) * 512 + slot] = split2(accO[nt][2] * inv1, accO[nt][3] * inv1);
    }
}

// ---------- launch ----------
extern "C" void kernel_launch(void *const *d_in, const int *in_sizes, int n_in, void *d_out, int out_size) {
    const float *x = (const float *)d_in[0];
    const float *Wptr[4] = {(const float *)d_in[1], (const float *)d_in[2], (const float *)d_in[3],
                            (const float *)d_in[4]};
    float *out = (float *)d_out;

    uint2 *pxs, *pQ, *pK, *pA;
    float *pV;
    uint2 *pW;
    cudaGetSymbolAddress((void **)&pxs, g_xs);
    cudaGetSymbolAddress((void **)&pW, g_Ws);
    cudaGetSymbolAddress((void **)&pQ, g_Qh);
    cudaGetSymbolAddress((void **)&pK, g_Kh);
    cudaGetSymbolAddress((void **)&pV, g_Vf);
    cudaGetSymbolAddress((void **)&pA, g_Ah);

    cudaFuncSetAttribute(gemm_kernel, cudaFuncAttributeMaxDynamicSharedMemorySize, GEMM_SMEM);
    cudaFuncSetAttribute(attn_kernel, cudaFuncAttributeMaxDynamicSharedMemorySize, ATTN_SMEM);

    // split passes
    split_kernel<<<M_TOT * 512 / 256, 256>>>(x, pxs, M_TOT * 512);
    for (int i = 0; i < 4; i++)
        split_kernel<<<D_MODEL * 512 / 256, 256>>>(Wptr[i], pW + (size_t)i * D_MODEL * 512, D_MODEL * 512);

    dim3 gg(8, 64);
    gemm_kernel<<<gg, 256, GEMM_SMEM>>>(pxs, pW + 0 * (size_t)D_MODEL * 512, pQ, 1);
    gemm_kernel<<<gg, 256, GEMM_SMEM>>>(pxs, pW + 1 * (size_t)D_MODEL * 512, pK, 1);
    gemm_kernel<<<gg, 256, GEMM_SMEM>>>(pxs, pW + 2 * (size_t)D_MODEL * 512, pV, 2);
    attn_kernel<<<dim3(SEQ / 128, BATCH * N_HEADS), 256, ATTN_SMEM>>>(pQ, pK, pV, pA);
    gemm_kernel<<<gg, 256, GEMM_SMEM>>>(pA, pW + 3 * (size_t)D_MODEL * 512, out, 0);
}

// round 7
// speedup vs baseline: 1.6093x; 1.0167x over previous
#include <cuda_runtime.h>
#include <cuda_bf16.h>
#include <cstdint>

#define D_MODEL 1024
#define N_HEADS 16
#define HEAD_DIM 64
#define BATCH 4
#define SEQ 2048
#define M_TOT 8192  // BATCH*SEQ

// ---- scratch (device globals per allocation-free rule) ----
__device__ uint2 g_xs[M_TOT * 512];          // x split, interleaved {hi2,lo2} per k-pair
__device__ uint2 g_Ws[4][D_MODEL * 512];     // Wq,Wk,Wv,Wo split
__device__ uint2 g_Qh[M_TOT * 512];          // Q scatter (B,H,S,32) interleaved
__device__ uint2 g_Kh[M_TOT * 512];          // K scatter
__device__ uint32_t g_Vh[M_TOT * 512];       // V scatter hi plane (B,H,S,32 uint32-pairs)
__device__ uint32_t g_Vl[M_TOT * 512];       // V scatter lo plane
__device__ uint2 g_Ah[M_TOT * 512];          // attention out, split, (B,S,D/2)

// ---------- helpers ----------
__device__ __forceinline__ uint2 split2(float f0, float f1) {
    __nv_bfloat16 h0 = __float2bfloat16_rn(f0), h1 = __float2bfloat16_rn(f1);
    float r0 = f0 - __bfloat162float(h0), r1 = f1 - __bfloat162float(h1);
    __nv_bfloat16 l0 = __float2bfloat16_rn(r0), l1 = __float2bfloat16_rn(r1);
    uint2 u;
    u.x = ((uint32_t)__bfloat16_as_ushort(h1) << 16) | __bfloat16_as_ushort(h0);
    u.y = ((uint32_t)__bfloat16_as_ushort(l1) << 16) | __bfloat16_as_ushort(l0);
    return u;
}

__device__ __forceinline__ void mma_bf16(float c[4], uint32_t a0, uint32_t a1, uint32_t a2, uint32_t a3,
                                         uint32_t b0, uint32_t b1) {
    asm volatile(
        "mma.sync.aligned.m16n8k16.row.col.f32.bf16.bf16.f32 "
        "{%0,%1,%2,%3}, {%4,%5,%6,%7}, {%8,%9}, {%0,%1,%2,%3};\n"
        : "+f"(c[0]), "+f"(c[1]), "+f"(c[2]), "+f"(c[3])
        : "r"(a0), "r"(a1), "r"(a2), "r"(a3), "r"(b0), "r"(b1));
}

__device__ __forceinline__ void ldmx4t(uint32_t &b0, uint32_t &b1, uint32_t &b2, uint32_t &b3, uint32_t addr) {
    asm volatile("ldmatrix.sync.aligned.m8n8.x4.trans.shared.b16 {%0,%1,%2,%3}, [%4];"
                 : "=r"(b0), "=r"(b1), "=r"(b2), "=r"(b3)
                 : "r"(addr));
}

__device__ __forceinline__ void cpa8(uint32_t saddr, const void *g) {
    asm volatile("cp.async.ca.shared.global [%0], [%1], 8;\n" ::"r"(saddr), "l"(g));
}
__device__ __forceinline__ void cpa16(uint32_t saddr, const void *g) {
    asm volatile("cp.async.cg.shared.global [%0], [%1], 16;\n" ::"r"(saddr), "l"(g));
}

// ---------- split pass: fp32 -> interleaved {hi2,lo2} ----------
__global__ void __launch_bounds__(256) split_kernel(const float *__restrict__ src, uint2 *__restrict__ dst, int npairs) {
    int i = blockIdx.x * 256 + threadIdx.x;
    if (i < npairs) {
        float2 f = *(const float2 *)(src + 2 * (size_t)i);
        dst[i] = split2(f.x, f.y);
    }
}

// ---------- GEMM: C[m,n] = sum_k A[m,k]*B[n,k], bf16x3, operands pre-split ----------
#define LDAU 19  // u64 slots per row (16 data + 3 pad)
#define GEMM_SMEM (2 * 2 * 128 * LDAU * 8)

__global__ void __launch_bounds__(256) gemm_kernel(const uint2 *__restrict__ A, const uint2 *__restrict__ B,
                                                   void *__restrict__ Cout, void *__restrict__ Cout2, int mode) {
    extern __shared__ uint2 smg[];
    uint2 *As = smg;                 // [2][128][LDAU]
    uint2 *Bs = smg + 2 * 128 * LDAU;
    uint32_t smb;
    asm("{ .reg .u64 t; cvta.to.shared.u64 t, %1; cvt.u32.u64 %0, t; }" : "=r"(smb) : "l"(smg));
    const int tid = threadIdx.x, lane = tid & 31, w = tid >> 5;
    const int m0 = blockIdx.y * 128, n0 = blockIdx.x * 128;
    const int wm = (w >> 2) * 64, wn = (w & 3) * 32;
    const int gr = lane >> 2, gc = lane & 3;

    float acc[4][4][4];
#pragma unroll
    for (int i = 0; i < 4; i++)
#pragma unroll
        for (int j = 0; j < 4; j++)
#pragma unroll
            for (int k = 0; k < 4; k++) acc[i][j][k] = 0.f;

    auto load = [&](int kt, int stg) {
        const uint2 *Ag = A + (size_t)m0 * 512 + kt * 16;
        const uint2 *Bg = B + (size_t)n0 * 512 + kt * 16;
        uint32_t Ad = smb + (stg * 128 * LDAU) * 8;
        uint32_t Bd = smb + ((2 + stg) * 128 * LDAU) * 8;
#pragma unroll
        for (int i = 0; i < 4; i++) {
            int id = tid + i * 256;
            int r = id >> 3, c = (id & 7) * 2;
            cpa8(Ad + (r * LDAU + c) * 8, Ag + (size_t)r * 512 + c);
            cpa8(Ad + (r * LDAU + c + 1) * 8, Ag + (size_t)r * 512 + c + 1);
            cpa8(Bd + (r * LDAU + c) * 8, Bg + (size_t)r * 512 + c);
            cpa8(Bd + (r * LDAU + c + 1) * 8, Bg + (size_t)r * 512 + c + 1);
        }
    };

    load(0, 0);
    asm volatile("cp.async.commit_group;\n");

    for (int kt = 0; kt < 32; ++kt) {
        asm volatile("cp.async.wait_group 0;\n");
        __syncthreads();
        if (kt + 1 < 32) {
            load(kt + 1, (kt + 1) & 1);
            asm volatile("cp.async.commit_group;\n");
        }
        const uint2 *Ad = As + (kt & 1) * 128 * LDAU;
        const uint2 *Bd = Bs + (kt & 1) * 128 * LDAU;
#pragma unroll
        for (int ks = 0; ks < 2; ks++) {
            const int so = ks * 8;
            uint32_t ahi[4][4], alo[4][4], bhi[4][2], blo[4][2];
#pragma unroll
            for (int im = 0; im < 4; im++) {
                const uint2 *p = Ad + (wm + im * 16 + gr) * LDAU + so + gc;
                uint2 v0 = p[0], v1 = p[8 * LDAU], v2 = p[4], v3 = p[8 * LDAU + 4];
                ahi[im][0] = v0.x; ahi[im][1] = v1.x; ahi[im][2] = v2.x; ahi[im][3] = v3.x;
                alo[im][0] = v0.y; alo[im][1] = v1.y; alo[im][2] = v2.y; alo[im][3] = v3.y;
            }
#pragma unroll
            for (int in = 0; in < 4; in++) {
                const uint2 *p = Bd + (wn + in * 8 + gr) * LDAU + so + gc;
                uint2 u0 = p[0], u1 = p[4];
                bhi[in][0] = u0.x; bhi[in][1] = u1.x;
                blo[in][0] = u0.y; blo[in][1] = u1.y;
            }
#pragma unroll
            for (int im = 0; im < 4; im++)
#pragma unroll
                for (int in = 0; in < 4; in++) {
                    mma_bf16(acc[im][in], ahi[im][0], ahi[im][1], ahi[im][2], ahi[im][3], bhi[in][0], bhi[in][1]);
                    mma_bf16(acc[im][in], alo[im][0], alo[im][1], alo[im][2], alo[im][3], bhi[in][0], bhi[in][1]);
                    mma_bf16(acc[im][in], ahi[im][0], ahi[im][1], ahi[im][2], ahi[im][3], blo[in][0], blo[in][1]);
                }
        }
        __syncthreads();
    }

#pragma unroll
    for (int im = 0; im < 4; im++)
#pragma unroll
        for (int in = 0; in < 4; in++) {
            int gm = m0 + wm + im * 16 + gr;
            int gn = n0 + wn + in * 8 + gc * 2;
            float c0 = acc[im][in][0], c1 = acc[im][in][1], c2 = acc[im][in][2], c3 = acc[im][in][3];
            if (mode == 0) {
                float *Cf = (float *)Cout;
                *(float2 *)(Cf + (size_t)gm * 1024 + gn) = make_float2(c0, c1);
                *(float2 *)(Cf + (size_t)(gm + 8) * 1024 + gn) = make_float2(c2, c3);
            } else {
                int b = gm >> 11, s2 = gm & 2047, h = gn >> 6, dd = gn & 63;
                if (mode == 1) {
                    uint2 *Ch = (uint2 *)Cout;
                    uint2 *dst = Ch + ((size_t)((b << 4) | h) * 2048 + s2) * 32 + (dd >> 1);
                    dst[0] = split2(c0, c1);
                    dst[8 * 32] = split2(c2, c3);
                } else {
                    // V: hi/lo bf16 planes (B,H,S,32 uint32-pairs)
                    uint32_t *Vh = (uint32_t *)Cout, *Vl = (uint32_t *)Cout2;
                    size_t idx = ((size_t)((b << 4) | h) * 2048 + s2) * 32 + (dd >> 1);
                    uint2 uA = split2(c0, c1);
                    Vh[idx] = uA.x; Vl[idx] = uA.y;
                    uint2 uB = split2(c2, c3);
                    Vh[idx + 8 * 32] = uB.x; Vl[idx + 8 * 32] = uB.y;
                }
            }
        }
}

// ---------- Flash attention: q-tile 128 (8 warps x 16 rows), kv-tile 64 double-buffered ----------
#define LQ 35
// smem layout (bytes): Qs [128][35] uint2 @0 (35840), Ks[2][64][35] uint2 @35840 (2x17920),
// Vh[2][64][72] bf16 @71680 (2x9216), Vl[2][64][72] bf16 @90112 (2x9216). total 108544.
#define QS_OFF 0
#define KS_OFF 35840
#define VH_OFF 71680
#define VL_OFF 90112
#define ATTN_SMEM 108544

__global__ void __launch_bounds__(256, 2) attn_kernel(const uint2 *__restrict__ Q, const uint2 *__restrict__ K,
                                                      const uint32_t *__restrict__ Vh,
                                                      const uint32_t *__restrict__ Vl, uint2 *__restrict__ O) {
    extern __shared__ char smab[];
    uint32_t smb;
    asm("{ .reg .u64 t; cvta.to.shared.u64 t, %1; cvt.u32.u64 %0, t; }" : "=r"(smb) : "l"(smab));
    uint2 *Qs = (uint2 *)smab;
    const int tid = threadIdx.x, lane = tid & 31, w = tid >> 5;
    const int qt = (int)gridDim.x - 1 - (int)blockIdx.x;  // long CTAs first
    const int bh = blockIdx.y;
    const int gr = lane >> 2, gc = lane & 3;
    const size_t hb = (size_t)bh * SEQ;
    // ldmatrix lane-address components
    const uint32_t vrow = ((lane >> 3) & 1) * 8 + (lane & 7);
    const uint32_t vcol = (lane >> 4) * 8;

    {  // Q tile once (plain stores; covered by first barrier)
        const uint2 *Qg = Q + (hb + qt * 128) * 32;
#pragma unroll
        for (int i = 0; i < 16; i++) {
            int id = tid + i * 256;
            int r = id >> 5, c = id & 31;
            Qs[r * LQ + c] = Qg[r * 32 + c];
        }
    }

    auto loadKV = [&](int kt, int s) {
        const uint2 *Kg = K + (hb + kt * 64) * 32;
        const uint32_t kb = smb + KS_OFF + s * 17920;
#pragma unroll
        for (int i = 0; i < 8; i++) {
            int id = tid + i * 256;
            int r = id >> 5, c = id & 31;
            cpa8(kb + (r * LQ + c) * 8, Kg + r * 32 + c);
        }
        const uint32_t *Vhg = Vh + (hb + kt * 64) * 32;
        const uint32_t *Vlg = Vl + (hb + kt * 64) * 32;
        const uint32_t vhb = smb + VH_OFF + s * 9216;
        const uint32_t vlb = smb + VL_OFF + s * 9216;
#pragma unroll
        for (int i = 0; i < 2; i++) {  // 512 ids: 64 rows x 8 chunks of 16B
            int id = tid + i * 256;
            int r = id >> 3, c = id & 7;
            cpa16(vhb + r * 144 + c * 16, Vhg + r * 32 + c * 4);
            cpa16(vlb + r * 144 + c * 16, Vlg + r * 32 + c * 4);
        }
    };

    float accO[8][4];
#pragma unroll
    for (int i = 0; i < 8; i++)
#pragma unroll
        for (int j = 0; j < 4; j++) accO[i][j] = 0.f;
    float m0r = -1e30f, m1r = -1e30f, l0 = 0.f, l1 = 0.f;
    const int qlast = qt * 128 + w * 16 + 15;
    const int nkt = 2 * qt + 2;

    loadKV(0, 0);
    asm volatile("cp.async.commit_group;\n");

    for (int kt = 0; kt < nkt; ++kt) {
        const int s = kt & 1;
        __syncthreads();  // all warps done with buffer s^1 (previous compute)
        if (kt + 1 < nkt) {
            loadKV(kt + 1, s ^ 1);
            asm volatile("cp.async.commit_group;\n");
            asm volatile("cp.async.wait_group 1;\n");  // stage kt complete; kt+1 in flight
        } else {
            asm volatile("cp.async.wait_group 0;\n");
        }
        __syncthreads();  // stage kt visible to all
        if (kt * 64 > qlast) continue;  // warp fully above diagonal

        const uint2 *Ks = (const uint2 *)(smab + KS_OFF + s * 17920);
        const uint32_t vhb = smb + VH_OFF + s * 9216;
        const uint32_t vlb = smb + VL_OFF + s * 9216;

        // S = Q K^T (16 q-rows x 64 kv)
        float sr[8][4];
#pragma unroll
        for (int nt = 0; nt < 8; nt++)
#pragma unroll
            for (int j = 0; j < 4; j++) sr[nt][j] = 0.f;

#pragma unroll
        for (int ks = 0; ks < 4; ks++) {
            const int so = ks * 8;
            const uint2 *ap = Qs + (w * 16 + gr) * LQ + so + gc;
            uint2 a0 = ap[0], a1 = ap[8 * LQ], a2 = ap[4], a3 = ap[8 * LQ + 4];
#pragma unroll
            for (int nt = 0; nt < 8; nt++) {
                const uint2 *bp = Ks + (nt * 8 + gr) * LQ + so + gc;
                uint2 b0 = bp[0], b1 = bp[4];
                mma_bf16(sr[nt], a0.x, a1.x, a2.x, a3.x, b0.x, b1.x);
                mma_bf16(sr[nt], a0.y, a1.y, a2.y, a3.y, b0.x, b1.x);
                mma_bf16(sr[nt], a0.x, a1.x, a2.x, a3.x, b0.y, b1.y);
            }
        }

        // scale + causal mask + row stats
        const bool needm = (kt * 64 + 63) > (qt * 128 + w * 16);
        const int qg0 = qt * 128 + w * 16 + gr;
        float mx0 = -1e30f, mx1 = -1e30f;
#pragma unroll
        for (int nt = 0; nt < 8; nt++) {
            int kg = kt * 64 + nt * 8 + gc * 2;
#pragma unroll
            for (int j = 0; j < 4; j++) {
                float v = sr[nt][j] * 0.125f;
                if (needm && (kg + (j & 1)) > (qg0 + ((j >> 1) << 3))) v = -1e30f;
                sr[nt][j] = v;
            }
            mx0 = fmaxf(mx0, fmaxf(sr[nt][0], sr[nt][1]));
            mx1 = fmaxf(mx1, fmaxf(sr[nt][2], sr[nt][3]));
        }
        mx0 = fmaxf(mx0, __shfl_xor_sync(0xffffffffu, mx0, 1));
        mx0 = fmaxf(mx0, __shfl_xor_sync(0xffffffffu, mx0, 2));
        mx1 = fmaxf(mx1, __shfl_xor_sync(0xffffffffu, mx1, 1));
        mx1 = fmaxf(mx1, __shfl_xor_sync(0xffffffffu, mx1, 2));
        float mn0 = fmaxf(m0r, mx0), mn1 = fmaxf(m1r, mx1);
        float alpha0 = __expf(m0r - mn0), alpha1 = __expf(m1r - mn1);
        m0r = mn0; m1r = mn1;

        float rs0 = 0.f, rs1 = 0.f;
#pragma unroll
        for (int nt = 0; nt < 8; nt++) {
            float p0 = __expf(sr[nt][0] - mn0);
            float p1 = __expf(sr[nt][1] - mn0);
            float p2 = __expf(sr[nt][2] - mn1);
            float p3 = __expf(sr[nt][3] - mn1);
            sr[nt][0] = p0; sr[nt][1] = p1; sr[nt][2] = p2; sr[nt][3] = p3;
            rs0 += p0 + p1;
            rs1 += p2 + p3;
        }
        rs0 += __shfl_xor_sync(0xffffffffu, rs0, 1);
        rs0 += __shfl_xor_sync(0xffffffffu, rs0, 2);
        rs1 += __shfl_xor_sync(0xffffffffu, rs1, 1);
        rs1 += __shfl_xor_sync(0xffffffffu, rs1, 2);
        l0 = l0 * alpha0 + rs0;
        l1 = l1 * alpha1 + rs1;
#pragma unroll
        for (int nt = 0; nt < 8; nt++) {
            accO[nt][0] *= alpha0; accO[nt][1] *= alpha0;
            accO[nt][2] *= alpha1; accO[nt][3] *= alpha1;
        }

        // O += P V   (P split in registers; V B-fragments via ldmatrix.x4.trans on hi/lo planes)
#pragma unroll
        for (int t = 0; t < 4; t++) {
            uint2 u0 = split2(sr[2 * t][0], sr[2 * t][1]);
            uint2 u1 = split2(sr[2 * t][2], sr[2 * t][3]);
            uint2 u2 = split2(sr[2 * t + 1][0], sr[2 * t + 1][1]);
            uint2 u3 = split2(sr[2 * t + 1][2], sr[2 * t + 1][3]);
            const uint32_t rowoff = (t * 16 + vrow) * 144 + vcol * 2;
#pragma unroll
            for (int ntp = 0; ntp < 4; ntp++) {
                uint32_t bh0, bh1, bh2, bh3, bl0, bl1, bl2, bl3;
                ldmx4t(bh0, bh1, bh2, bh3, vhb + rowoff + ntp * 32);
                ldmx4t(bl0, bl1, bl2, bl3, vlb + rowoff + ntp * 32);
                mma_bf16(accO[2 * ntp], u0.x, u1.x, u2.x, u3.x, bh0, bh1);
                mma_bf16(accO[2 * ntp], u0.y, u1.y, u2.y, u3.y, bh0, bh1);
                mma_bf16(accO[2 * ntp], u0.x, u1.x, u2.x, u3.x, bl0, bl1);
                mma_bf16(accO[2 * ntp + 1], u0.x, u1.x, u2.x, u3.x, bh2, bh3);
                mma_bf16(accO[2 * ntp + 1], u0.y, u1.y, u2.y, u3.y, bh2, bh3);
                mma_bf16(accO[2 * ntp + 1], u0.x, u1.x, u2.x, u3.x, bl2, bl3);
            }
        }
    }

    // epilogue: write split interleaved concat layout (B,S,D/2)
    float inv0 = 1.f / l0, inv1 = 1.f / l1;
    int b = bh >> 4, h = bh & 15;
    int q0 = qt * 128 + w * 16 + gr;
#pragma unroll
    for (int nt = 0; nt < 8; nt++) {
        int slot = h * 32 + nt * 4 + gc;
        O[((size_t)(b * SEQ + q0)) * 512 + slot] = split2(accO[nt][0] * inv0, accO[nt][1] * inv0);
        O[((size_t)(b * SEQ + q0 + 8)) * 512 + slot] = split2(accO[nt][2] * inv1, accO[nt][3] * inv1);
    }
}

// ---------- launch ----------
extern "C" void kernel_launch(void *const *d_in, const int *in_sizes, int n_in, void *d_out, int out_size) {
    const float *x = (const float *)d_in[0];
    const float *Wptr[4] = {(const float *)d_in[1], (const float *)d_in[2], (const float *)d_in[3],
                            (const float *)d_in[4]};
    float *out = (float *)d_out;

    uint2 *pxs, *pQ, *pK, *pA, *pW;
    uint32_t *pVh, *pVl;
    cudaGetSymbolAddress((void **)&pxs, g_xs);
    cudaGetSymbolAddress((void **)&pW, g_Ws);
    cudaGetSymbolAddress((void **)&pQ, g_Qh);
    cudaGetSymbolAddress((void **)&pK, g_Kh);
    cudaGetSymbolAddress((void **)&pVh, g_Vh);
    cudaGetSymbolAddress((void **)&pVl, g_Vl);
    cudaGetSymbolAddress((void **)&pA, g_Ah);

    cudaFuncSetAttribute(gemm_kernel, cudaFuncAttributeMaxDynamicSharedMemorySize, GEMM_SMEM);
    cudaFuncSetAttribute(attn_kernel, cudaFuncAttributeMaxDynamicSharedMemorySize, ATTN_SMEM);

    // split passes
    split_kernel<<<M_TOT * 512 / 256, 256>>>(x, pxs, M_TOT * 512);
    for (int i = 0; i < 4; i++)
        split_kernel<<<D_MODEL * 512 / 256, 256>>>(Wptr[i], pW + (size_t)i * D_MODEL * 512, D_MODEL * 512);

    dim3 gg(8, 64);
    gemm_kernel<<<gg, 256, GEMM_SMEM>>>(pxs, pW + 0 * (size_t)D_MODEL * 512, pQ, nullptr, 1);
    gemm_kernel<<<gg, 256, GEMM_SMEM>>>(pxs, pW + 1 * (size_t)D_MODEL * 512, pK, nullptr, 1);
    gemm_kernel<<<gg, 256, GEMM_SMEM>>>(pxs, pW + 2 * (size_t)D_MODEL * 512, pVh, pVl, 2);
    attn_kernel<<<dim3(SEQ / 128, BATCH * N_HEADS), 256, ATTN_SMEM>>>(pQ, pK, pVh, pVl, pA);
    gemm_kernel<<<gg, 256, GEMM_SMEM>>>(pA, pW + 3 * (size_t)D_MODEL * 512, out, nullptr, 0);
}